// round 1
// baseline (speedup 1.0000x reference)
#include <cuda_runtime.h>
#include <math.h>

// ---------------------------------------------------------------------------
// Problem constants
// ---------------------------------------------------------------------------
static const int NB   = 4;      // batch
static const int CPc  = 256;    // Cp
static const int PLc  = 64;     // planes
static const int NQc  = 2304;   // 48*48 query positions

// per-scale sizes
static const int CRs[5] = {64, 256, 512, 1024, 2048};
static const int Ms [5] = {2304, 2304, 576, 144, 36};

// ---------------------------------------------------------------------------
// Scratch (device globals; no allocation allowed)
// ---------------------------------------------------------------------------
__device__ float g_T[NB * PLc * NQc];        // t = t_w @ persp, [b][64][2304]
__device__ float g_P[NB * PLc * NQc];        // p projection      [b][64][M]
__device__ float g_G[NB * PLc * NQc];        // g projection      [b][64][M]
__device__ float g_L[NB * NQc * NQc];        // logits/attention  [b][2304][M]
__device__ float g_O[NB * NQc * PLc];        // att @ g^T         [b][2304][64]
__device__ float g_Z[NB * CPc * NQc];        // z_w @ O_view      [b][256][2304]
__device__ float g_mean[CPc];
__device__ float g_istd[CPc];

// ---------------------------------------------------------------------------
// Generic tiled SGEMM.
//  C[M,N] = op(A) * op(B)
//  TA=false: A row-major [M,K].   TA=true: A stored [K,M] (ld = M).
//  TB=false: B row-major [K,N].   TB=true: B stored [N,K] (ld = K).
//  Batched over blockIdx.z with element strides sA/sB/sC (0 => shared operand).
//  BM=BN=64, BK=16, 256 threads, 4x4 per-thread micro-tile. Fully bounds-checked.
// ---------------------------------------------------------------------------
template<bool TA, bool TB>
__global__ void sgemm_kernel(const float* __restrict__ A,
                             const float* __restrict__ Bm,
                             float* __restrict__ C,
                             int M, int N, int K,
                             long sA, long sB, long sC)
{
    const int BMt = 64, BNt = 64, BKt = 16;
    __shared__ float As[BKt][BMt + 1];
    __shared__ float Bs[BKt][BNt + 1];

    A  += (long)blockIdx.z * sA;
    Bm += (long)blockIdx.z * sB;
    C  += (long)blockIdx.z * sC;

    const int m0 = blockIdx.y * BMt;
    const int n0 = blockIdx.x * BNt;
    const int tid = threadIdx.x;
    const int ty = tid >> 4;     // 0..15
    const int tx = tid & 15;     // 0..15

    float acc[4][4];
#pragma unroll
    for (int i = 0; i < 4; i++)
#pragma unroll
        for (int j = 0; j < 4; j++) acc[i][j] = 0.f;

    for (int k0 = 0; k0 < K; k0 += BKt) {
        // --- load A tile -> As[k][m] ---
#pragma unroll
        for (int l = 0; l < 4; l++) {
            int e = tid + l * 256;
            int m, k;
            if (!TA) { m = e >> 4;  k = e & 15; }       // coalesced over k
            else     { k = e >> 6;  m = e & 63; }       // coalesced over m
            int gm = m0 + m, gk = k0 + k;
            float v = 0.f;
            if (gm < M && gk < K)
                v = TA ? A[(long)gk * M + gm] : A[(long)gm * K + gk];
            As[k][m] = v;
        }
        // --- load B tile -> Bs[k][n] ---
#pragma unroll
        for (int l = 0; l < 4; l++) {
            int e = tid + l * 256;
            int k, n;
            if (!TB) { k = e >> 6;  n = e & 63; }       // coalesced over n
            else     { n = e >> 4;  k = e & 15; }       // coalesced over k
            int gk = k0 + k, gn = n0 + n;
            float v = 0.f;
            if (gk < K && gn < N)
                v = TB ? Bm[(long)gn * K + gk] : Bm[(long)gk * N + gn];
            Bs[k][n] = v;
        }
        __syncthreads();

#pragma unroll
        for (int kk = 0; kk < BKt; kk++) {
            float a[4], b[4];
#pragma unroll
            for (int i = 0; i < 4; i++) a[i] = As[kk][ty * 4 + i];
#pragma unroll
            for (int j = 0; j < 4; j++) b[j] = Bs[kk][tx * 4 + j];
#pragma unroll
            for (int i = 0; i < 4; i++)
#pragma unroll
                for (int j = 0; j < 4; j++)
                    acc[i][j] += a[i] * b[j];
        }
        __syncthreads();
    }

#pragma unroll
    for (int i = 0; i < 4; i++) {
        int gm = m0 + ty * 4 + i;
        if (gm >= M) continue;
#pragma unroll
        for (int j = 0; j < 4; j++) {
            int gn = n0 + tx * 4 + j;
            if (gn < N) C[(long)gm * N + gn] = acc[i][j];
        }
    }
}

// ---------------------------------------------------------------------------
// Row softmax (in place). One block per row, rows are contiguous length Mi.
// ---------------------------------------------------------------------------
__global__ void softmax_rows_kernel(float* __restrict__ L, int Mi)
{
    float* p = L + (long)blockIdx.x * Mi;
    const int t = threadIdx.x;

    float v[9];
    int cnt = 0;
    float mx = -INFINITY;
    for (int m = t; m < Mi; m += 256) {
        v[cnt] = p[m];
        mx = fmaxf(mx, v[cnt]);
        cnt++;
    }

    __shared__ float red[256];
    red[t] = mx;
    __syncthreads();
#pragma unroll
    for (int s = 128; s > 0; s >>= 1) {
        if (t < s) red[t] = fmaxf(red[t], red[t + s]);
        __syncthreads();
    }
    mx = red[0];
    __syncthreads();

    float sum = 0.f;
    for (int i = 0; i < cnt; i++) { v[i] = __expf(v[i] - mx); sum += v[i]; }

    red[t] = sum;
    __syncthreads();
#pragma unroll
    for (int s = 128; s > 0; s >>= 1) {
        if (t < s) red[t] += red[t + s];
        __syncthreads();
    }
    float inv = 1.f / red[0];

    cnt = 0;
    for (int m = t; m < Mi; m += 256) p[m] = v[cnt++] * inv;
}

// ---------------------------------------------------------------------------
// BN stats: mean & 1/sqrt(var+eps) per channel over (b, spatial). Biased var.
// ---------------------------------------------------------------------------
__global__ void bn_stats_kernel(const float* __restrict__ Z,
                                float* __restrict__ mean,
                                float* __restrict__ istd)
{
    const int c = blockIdx.x;
    const int t = threadIdx.x;
    const int CNT = NB * NQc;   // 9216
    float s = 0.f, s2 = 0.f;
    for (int idx = t; idx < CNT; idx += 256) {
        int b = idx / NQc, sp = idx - b * NQc;
        float v = Z[((long)b * CPc + c) * NQc + sp];
        s += v; s2 += v * v;
    }
    __shared__ float rs[256], rs2[256];
    rs[t] = s; rs2[t] = s2;
    __syncthreads();
#pragma unroll
    for (int k = 128; k > 0; k >>= 1) {
        if (t < k) { rs[t] += rs[t + k]; rs2[t] += rs2[t + k]; }
        __syncthreads();
    }
    if (t == 0) {
        float m  = rs[0] / (float)CNT;
        float var = rs2[0] / (float)CNT - m * m;
        mean[c] = m;
        istd[c] = rsqrtf(var + 1e-5f);
    }
}

// ---------------------------------------------------------------------------
// Normalize + affine + accumulate into output.
// ---------------------------------------------------------------------------
__global__ void bn_apply_kernel(const float* __restrict__ Z,
                                const float* __restrict__ mean,
                                const float* __restrict__ istd,
                                const float* __restrict__ gamma,
                                const float* __restrict__ beta,
                                float* __restrict__ out, int first)
{
    long i = (long)blockIdx.x * 256 + threadIdx.x;   // over NB*CPc*NQc
    int c = (int)((i / NQc) % CPc);
    float v = (Z[i] - mean[c]) * istd[c] * gamma[c] + beta[c];
    if (first) out[i] = v;
    else       out[i] += v;
}

// ---------------------------------------------------------------------------
// Host launch
// ---------------------------------------------------------------------------
extern "C" void kernel_launch(void* const* d_in, const int* in_sizes, int n_in,
                              void* d_out, int out_size)
{
    (void)in_sizes; (void)n_in; (void)out_size;

    const float* persp = (const float*)d_in[0];
    const float* resp[5] = {
        (const float*)d_in[1], (const float*)d_in[2], (const float*)d_in[3],
        (const float*)d_in[4], (const float*)d_in[5] };
    const float* t_w = (const float*)d_in[6];
    const float* z_w = (const float*)d_in[7];
    float* out = (float*)d_out;

    float *T, *P, *G, *L, *O, *Z, *mean, *istd;
    cudaGetSymbolAddress((void**)&T,    g_T);
    cudaGetSymbolAddress((void**)&P,    g_P);
    cudaGetSymbolAddress((void**)&G,    g_G);
    cudaGetSymbolAddress((void**)&L,    g_L);
    cudaGetSymbolAddress((void**)&O,    g_O);
    cudaGetSymbolAddress((void**)&Z,    g_Z);
    cudaGetSymbolAddress((void**)&mean, g_mean);
    cudaGetSymbolAddress((void**)&istd, g_istd);

    // ---- T = t_w[64,256] @ persp[b][256,2304]  (shared across scales) ----
    {
        dim3 grid((NQc + 63) / 64, (PLc + 63) / 64, NB);
        sgemm_kernel<false, false><<<grid, 256>>>(
            t_w, persp, T, PLc, NQc, CPc,
            0L, (long)CPc * NQc, (long)PLc * NQc);
    }

    for (int i = 0; i < 5; i++) {
        const int Cr = CRs[i];
        const int Mi = Ms[i];
        const float* p_w   = (const float*)d_in[8  + 4 * i];
        const float* g_wt  = (const float*)d_in[9  + 4 * i];
        const float* gamma = (const float*)d_in[10 + 4 * i];
        const float* beta  = (const float*)d_in[11 + 4 * i];

        // P = p_w[64,Cr] @ resp[b][Cr,Mi]
        {
            dim3 grid((Mi + 63) / 64, 1, NB);
            sgemm_kernel<false, false><<<grid, 256>>>(
                p_w, resp[i], P, PLc, Mi, Cr,
                0L, (long)Cr * Mi, (long)PLc * Mi);
        }
        // G = g_w[64,Cr] @ resp[b][Cr,Mi]
        {
            dim3 grid((Mi + 63) / 64, 1, NB);
            sgemm_kernel<false, false><<<grid, 256>>>(
                g_wt, resp[i], G, PLc, Mi, Cr,
                0L, (long)Cr * Mi, (long)PLc * Mi);
        }
        // L = T^T[2304,64] @ P[64,Mi]   (TA: A stored [K=64, M=2304])
        {
            dim3 grid((Mi + 63) / 64, (NQc + 63) / 64, NB);
            sgemm_kernel<true, false><<<grid, 256>>>(
                T, P, L, NQc, Mi, PLc,
                (long)PLc * NQc, (long)PLc * Mi, (long)NQc * Mi);
        }
        // softmax over rows of L
        softmax_rows_kernel<<<NB * NQc, 256>>>(L, Mi);

        // O = A[2304,Mi] @ G^T   (TB: B stored [N=64, K=Mi])
        {
            dim3 grid((PLc + 63) / 64, (NQc + 63) / 64, NB);
            sgemm_kernel<false, true><<<grid, 256>>>(
                L, G, O, NQc, PLc, Mi,
                (long)NQc * Mi, (long)PLc * Mi, (long)NQc * PLc);
        }
        // Z = z_w[256,64] @ O_view[64,2304]  (no-permute reshape == flat reinterpret)
        {
            dim3 grid((NQc + 63) / 64, (CPc + 63) / 64, NB);
            sgemm_kernel<false, false><<<grid, 256>>>(
                z_w, O, Z, CPc, NQc, PLc,
                0L, (long)NQc * PLc, (long)CPc * NQc);
        }
        // BN stats + apply (accumulate; first scale initializes d_out)
        bn_stats_kernel<<<CPc, 256>>>(Z, mean, istd);
        {
            long total = (long)NB * CPc * NQc;
            bn_apply_kernel<<<(unsigned)(total / 256), 256>>>(
                Z, mean, istd, gamma, beta, out, i == 0 ? 1 : 0);
        }
    }
}

// round 2
// speedup vs baseline: 1.6605x; 1.6605x over previous
#include <cuda_runtime.h>
#include <math.h>

// ---------------------------------------------------------------------------
// Problem constants
// ---------------------------------------------------------------------------
#define NB   4
#define CPc  256
#define PLc  64
#define NQc  2304

static const int CRs[5] = {64, 256, 512, 1024, 2048};
static const int Ms [5] = {2304, 2304, 576, 144, 36};

// ---------------------------------------------------------------------------
// Scratch (device globals)
// ---------------------------------------------------------------------------
__device__ float g_T  [NB * PLc * NQc];            // [b][64][2304] K-major
__device__ float g_PGw[2 * PLc * 2048];            // stacked p_w;g_w [128, Cr]
__device__ float g_PG [NB * 2 * PLc * NQc];        // [b][128][Mi]
__device__ float g_Lt [NB * NQc * NQc];            // logits^T [b][Mi][2304]
__device__ float g_O  [NB * NQc * PLc];            // [b][2304][64] row-major flat
__device__ float g_Z  [NB * CPc * NQc];            // [b][256][2304]
__device__ float g_mst[NB * NQc];                  // softmax col max
__device__ float g_siv[NB * NQc];                  // softmax 1/sum
__device__ float g_mean[CPc];
__device__ float g_istd[CPc];

// ---------------------------------------------------------------------------
// Fast exp on the FMA pipe (no MUFU). exp(x)=2^(x*log2e). |err| ~ 2e-6 rel.
// ---------------------------------------------------------------------------
__device__ __forceinline__ float fexp(float x)
{
    const float L2E = 1.4426950408889634f;
    float t = fmaf(x, L2E, 12582912.0f);          // round-to-nearest magic
    float n = t - 12582912.0f;
    float f = fmaf(x, L2E, -n);                   // f in [-0.5, 0.5]
    float p = 1.33335581e-3f;
    p = fmaf(p, f, 9.61812911e-3f);
    p = fmaf(p, f, 5.55041087e-2f);
    p = fmaf(p, f, 2.40226507e-1f);
    p = fmaf(p, f, 6.93147180e-1f);
    p = fmaf(p, f, 1.0f);
    int ni = (int)n;
    ni = max(-126, min(127, ni));
    return p * __int_as_float((ni + 127) << 23);
}

// ---------------------------------------------------------------------------
// Tiled SGEMM, 256 threads, BK=16, TMxTN microtile, float4 smem path.
//  TAR : A is row-major [M,K] (transpose-load);   else A is K-major [K,M].
//  TBR : B is row-major [N,K] (transpose-load);   else B is K-major [K,N].
//  EXPA: transform A elements v -> exp(v - mst[m]) on load; scale row by siv[m].
//  ATOM: atomicAdd into C (split-K partials).
//  Batched over blockIdx.z = b*ksplit + kz ; K range [kz*kchunk, ...).
// ---------------------------------------------------------------------------
template<int BM, int BN, int TM, int TN, bool TAR, bool TBR, bool EXPA, bool ATOM>
__global__ void __launch_bounds__(256) gemm_k(
    const float* __restrict__ A, const float* __restrict__ B, float* __restrict__ C,
    int M, int N, int K, int lda, int ldb, int ldc,
    long sA, long sB, long sC, int ksplit, int kchunk,
    const float* __restrict__ mst, const float* __restrict__ siv, int sStat)
{
    constexpr int BK = 16;
    static_assert((BM / TM) * (BN / TN) == 256, "256 threads");
    __shared__ float As[BK][BM];
    __shared__ float Bs[BK][BN + (TBR ? 1 : 0)];

    const int b  = blockIdx.z / ksplit;
    const int kz = blockIdx.z - b * ksplit;
    A += (long)b * sA;  B += (long)b * sB;  C += (long)b * sC;
    const float* mstp = EXPA ? (mst + (long)b * sStat) : nullptr;

    const int kbeg = kz * kchunk;
    const int kend = min(K, kbeg + kchunk);
    const int m0 = blockIdx.y * BM, n0 = blockIdx.x * BN;
    const int tid = threadIdx.x;
    constexpr int TX = BN / TN;
    const int ty = tid / TX, tx = tid % TX;

    float acc[TM][TN];
#pragma unroll
    for (int i = 0; i < TM; i++)
#pragma unroll
        for (int j = 0; j < TN; j++) acc[i][j] = 0.f;

    for (int k0 = kbeg; k0 < kend; k0 += BK) {
        // ---- load A tile ----
        if (!TAR) {
            constexpr int MV = BM / 4;
#pragma unroll
            for (int r = 0; r < BM * BK / (4 * 256); r++) {
                int e = tid + r * 256;
                int k = e / MV, mq = e - k * MV;
                int gm = m0 + mq * 4;
                float4 v = {0.f, 0.f, 0.f, 0.f};
                bool ok = (k0 + k < kend) && (gm + 3 < M);
                if (ok) {
                    v = *(const float4*)(A + (long)(k0 + k) * lda + gm);
                    if (EXPA) {
                        v.x = fexp(v.x - mstp[gm]);
                        v.y = fexp(v.y - mstp[gm + 1]);
                        v.z = fexp(v.z - mstp[gm + 2]);
                        v.w = fexp(v.w - mstp[gm + 3]);
                    }
                }
                *(float4*)&As[k][mq * 4] = v;
            }
        } else {
#pragma unroll
            for (int r = 0; r < BM * BK / (4 * 256); r++) {
                int e = tid + r * 256;
                int m = e / 4, kq = e - m * 4;
                int gm = m0 + m, gk = k0 + kq * 4;
                float4 v = {0.f, 0.f, 0.f, 0.f};
                if (gm < M && gk + 3 < kend) {
                    v = *(const float4*)(A + (long)gm * lda + gk);
                } else if (gm < M) {
                    float* vv = (float*)&v;
                    for (int q = 0; q < 4; q++)
                        if (gk + q < kend) vv[q] = A[(long)gm * lda + gk + q];
                }
                As[kq * 4 + 0][m] = v.x; As[kq * 4 + 1][m] = v.y;
                As[kq * 4 + 2][m] = v.z; As[kq * 4 + 3][m] = v.w;
            }
        }
        // ---- load B tile ----
        if (!TBR) {
            constexpr int NV = BN / 4;
#pragma unroll
            for (int r = 0; r < BN * BK / (4 * 256); r++) {
                int e = tid + r * 256;
                int k = e / NV, nq = e - k * NV;
                int gn = n0 + nq * 4;
                float4 v = {0.f, 0.f, 0.f, 0.f};
                if ((k0 + k < kend) && (gn + 3 < N))
                    v = *(const float4*)(B + (long)(k0 + k) * ldb + gn);
                *(float4*)&Bs[k][nq * 4] = v;
            }
        } else {
#pragma unroll
            for (int r = 0; r < BN * BK / (4 * 256); r++) {
                int e = tid + r * 256;
                int n = e / 4, kq = e - n * 4;
                int gn = n0 + n, gk = k0 + kq * 4;
                float4 v = {0.f, 0.f, 0.f, 0.f};
                if (gn < N && gk + 3 < kend) {
                    v = *(const float4*)(B + (long)gn * ldb + gk);
                } else if (gn < N) {
                    float* vv = (float*)&v;
                    for (int q = 0; q < 4; q++)
                        if (gk + q < kend) vv[q] = B[(long)gn * ldb + gk + q];
                }
                Bs[kq * 4 + 0][n] = v.x; Bs[kq * 4 + 1][n] = v.y;
                Bs[kq * 4 + 2][n] = v.z; Bs[kq * 4 + 3][n] = v.w;
            }
        }
        __syncthreads();

#pragma unroll
        for (int kk = 0; kk < BK; kk++) {
            float a[TM], bb[TN];
#pragma unroll
            for (int i = 0; i < TM; i += 4)
                *(float4*)&a[i] = *(const float4*)&As[kk][ty * TM + i];
            if (!TBR) {
#pragma unroll
                for (int j = 0; j < TN; j += 4)
                    *(float4*)&bb[j] = *(const float4*)&Bs[kk][tx * TN + j];
            } else {
#pragma unroll
                for (int j = 0; j < TN; j++) bb[j] = Bs[kk][tx * TN + j];
            }
#pragma unroll
            for (int i = 0; i < TM; i++)
#pragma unroll
                for (int j = 0; j < TN; j++)
                    acc[i][j] = fmaf(a[i], bb[j], acc[i][j]);
        }
        __syncthreads();
    }

    // ---- epilogue ----
#pragma unroll
    for (int i = 0; i < TM; i++) {
        int gm = m0 + ty * TM + i;
        if (gm >= M) continue;
        float sc = EXPA ? siv[(long)b * sStat + gm] : 1.f;
#pragma unroll
        for (int j = 0; j < TN; j++) {
            int gn = n0 + tx * TN + j;
            if (gn < N) {
                float v = EXPA ? acc[i][j] * sc : acc[i][j];
                if (ATOM) atomicAdd(&C[(long)gm * ldc + gn], v);
                else      C[(long)gm * ldc + gn] = v;
            }
        }
    }
}

// ---------------------------------------------------------------------------
// Softmax column stats over Lt [b][Mi][2304]: per column (b,n) compute max and
// 1/sum(exp(x-max)). Block = 64 columns x 4 mi-strips. grid = NB*2304/64.
// ---------------------------------------------------------------------------
__global__ void softmax_stats_k(const float* __restrict__ Lt,
                                float* __restrict__ mst, float* __restrict__ siv,
                                int Mi)
{
    __shared__ float red[4][64];
    const int c = threadIdx.x & 63;
    const int strip = threadIdx.x >> 6;
    const long col0 = (long)blockIdx.x * 64;
    const long b = (col0 + c) / NQc;
    const int  n = (int)((col0 + c) - b * NQc);
    const float* p = Lt + b * (long)Mi * NQc + n;

    float m = -1e30f;
    for (int mi = strip; mi < Mi; mi += 4) m = fmaxf(m, p[(long)mi * NQc]);
    red[strip][c] = m;
    __syncthreads();
    m = fmaxf(fmaxf(red[0][c], red[1][c]), fmaxf(red[2][c], red[3][c]));
    __syncthreads();

    float s = 0.f;
    for (int mi = strip; mi < Mi; mi += 4) s += fexp(p[(long)mi * NQc] - m);
    red[strip][c] = s;
    __syncthreads();
    if (strip == 0) {
        s = red[0][c] + red[1][c] + red[2][c] + red[3][c];
        mst[col0 + c] = m;
        siv[col0 + c] = 1.0f / s;
    }
}

// ---------------------------------------------------------------------------
// BN stats per channel (biased var, over b & spatial)
// ---------------------------------------------------------------------------
__global__ void bn_stats_k(const float* __restrict__ Z,
                           float* __restrict__ mean, float* __restrict__ istd)
{
    const int c = blockIdx.x;
    const int t = threadIdx.x;
    const int CNT = NB * NQc;
    float s = 0.f, s2 = 0.f;
    for (int idx = t; idx < CNT; idx += 256) {
        int b = idx / NQc, sp = idx - b * NQc;
        float v = Z[((long)b * CPc + c) * NQc + sp];
        s += v; s2 += v * v;
    }
    __shared__ float rs[256], rs2[256];
    rs[t] = s; rs2[t] = s2;
    __syncthreads();
#pragma unroll
    for (int k = 128; k > 0; k >>= 1) {
        if (t < k) { rs[t] += rs[t + k]; rs2[t] += rs2[t + k]; }
        __syncthreads();
    }
    if (t == 0) {
        float m = rs[0] / (float)CNT;
        float var = rs2[0] / (float)CNT - m * m;
        mean[c] = m;
        istd[c] = rsqrtf(var + 1e-5f);
    }
}

// ---------------------------------------------------------------------------
// Normalize + affine + accumulate (float4).
// ---------------------------------------------------------------------------
__global__ void bn_apply_k(const float* __restrict__ Z,
                           const float* __restrict__ mean, const float* __restrict__ istd,
                           const float* __restrict__ gamma, const float* __restrict__ beta,
                           float* __restrict__ out, int first)
{
    long i = ((long)blockIdx.x * 256 + threadIdx.x) * 4;
    int c = (int)((i / NQc) % CPc);
    float a = istd[c] * gamma[c];
    float bb = fmaf(-mean[c], a, beta[c]);
    float4 z = *(const float4*)(Z + i);
    float4 v;
    v.x = fmaf(z.x, a, bb); v.y = fmaf(z.y, a, bb);
    v.z = fmaf(z.z, a, bb); v.w = fmaf(z.w, a, bb);
    if (first) {
        *(float4*)(out + i) = v;
    } else {
        float4 o = *(const float4*)(out + i);
        o.x += v.x; o.y += v.y; o.z += v.z; o.w += v.w;
        *(float4*)(out + i) = o;
    }
}

// ---------------------------------------------------------------------------
// Host launch
// ---------------------------------------------------------------------------
extern "C" void kernel_launch(void* const* d_in, const int* in_sizes, int n_in,
                              void* d_out, int out_size)
{
    (void)in_sizes; (void)n_in; (void)out_size;

    const float* persp = (const float*)d_in[0];
    const float* resp[5] = {
        (const float*)d_in[1], (const float*)d_in[2], (const float*)d_in[3],
        (const float*)d_in[4], (const float*)d_in[5] };
    const float* t_w = (const float*)d_in[6];
    const float* z_w = (const float*)d_in[7];
    float* out = (float*)d_out;

    float *T, *PGw, *PG, *Lt, *O, *Z, *mst, *siv, *mean, *istd;
    cudaGetSymbolAddress((void**)&T,   g_T);
    cudaGetSymbolAddress((void**)&PGw, g_PGw);
    cudaGetSymbolAddress((void**)&PG,  g_PG);
    cudaGetSymbolAddress((void**)&Lt,  g_Lt);
    cudaGetSymbolAddress((void**)&O,   g_O);
    cudaGetSymbolAddress((void**)&Z,   g_Z);
    cudaGetSymbolAddress((void**)&mst, g_mst);
    cudaGetSymbolAddress((void**)&siv, g_siv);
    cudaGetSymbolAddress((void**)&mean, g_mean);
    cudaGetSymbolAddress((void**)&istd, g_istd);

    // ---- T = t_w[64,256] @ persp[b][256,2304] ----
    gemm_k<64, 128, 4, 8, true, false, false, false>
        <<<dim3(NQc / 128, 1, NB), 256>>>(
            t_w, persp, T, PLc, NQc, CPc,
            CPc, NQc, NQc,
            0L, (long)CPc * NQc, (long)PLc * NQc,
            1, CPc, nullptr, nullptr, 0);

    static const int OKS[5] = {4, 4, 2, 1, 1};   // O-GEMM split-K factors

    for (int i = 0; i < 5; i++) {
        const int Cr = CRs[i];
        const int Mi = Ms[i];
        const float* p_w   = (const float*)d_in[8  + 4 * i];
        const float* g_wt  = (const float*)d_in[9  + 4 * i];
        const float* gamma = (const float*)d_in[10 + 4 * i];
        const float* beta  = (const float*)d_in[11 + 4 * i];

        // stack weights: PGw = [p_w ; g_w]  -> [128, Cr]
        cudaMemcpyAsync(PGw,            p_w, (size_t)PLc * Cr * 4,
                        cudaMemcpyDeviceToDevice, 0);
        cudaMemcpyAsync(PGw + PLc * Cr, g_wt, (size_t)PLc * Cr * 4,
                        cudaMemcpyDeviceToDevice, 0);

        // ---- PG = PGw[128,Cr] @ resp[b][Cr,Mi]  (split-K over Cr, chunk 64) ----
        {
            int ks = Cr / 64;               // 1,4,8,16,32
            dim3 grid((Mi + 127) / 128, 1, NB * ks);
            if (ks > 1) {
                cudaMemsetAsync(PG, 0, (size_t)NB * 128 * Mi * 4, 0);
                gemm_k<128, 128, 8, 8, true, false, false, true>
                    <<<grid, 256>>>(PGw, resp[i], PG, 128, Mi, Cr,
                                    Cr, Mi, Mi,
                                    0L, (long)Cr * Mi, (long)128 * Mi,
                                    ks, 64, nullptr, nullptr, 0);
            } else {
                gemm_k<128, 128, 8, 8, true, false, false, false>
                    <<<grid, 256>>>(PGw, resp[i], PG, 128, Mi, Cr,
                                    Cr, Mi, Mi,
                                    0L, (long)Cr * Mi, (long)128 * Mi,
                                    1, Cr, nullptr, nullptr, 0);
            }
        }

        // ---- Lt[b][Mi][2304] = P^T @ T : A = P (K-major [64,Mi]), B = T ----
        {
            dim3 grid(NQc / 128, (Mi + 127) / 128, NB);
            gemm_k<128, 128, 8, 8, false, false, false, false>
                <<<grid, 256>>>(PG, T, Lt, Mi, NQc, PLc,
                                Mi, NQc, NQc,
                                (long)128 * Mi, (long)PLc * NQc, (long)Mi * NQc,
                                1, PLc, nullptr, nullptr, 0);
        }

        // ---- softmax column stats ----
        softmax_stats_k<<<NB * NQc / 64, 256>>>(Lt, mst, siv, Mi);

        // ---- O[b][2304][64] = softmax(Lt)^T @ G^T  (exp fused on A loads) ----
        {
            int ks = OKS[i];
            int kchunk = Mi / ks;
            dim3 grid(1, NQc / 128, NB * ks);
            if (ks > 1) {
                cudaMemsetAsync(O, 0, (size_t)NB * NQc * PLc * 4, 0);
                gemm_k<128, 64, 8, 4, false, true, true, true>
                    <<<grid, 256>>>(Lt, PG + (long)PLc * Mi, O, NQc, PLc, Mi,
                                    NQc, Mi, PLc,
                                    (long)Mi * NQc, (long)128 * Mi, (long)NQc * PLc,
                                    ks, kchunk, mst, siv, NQc);
            } else {
                gemm_k<128, 64, 8, 4, false, true, true, false>
                    <<<grid, 256>>>(Lt, PG + (long)PLc * Mi, O, NQc, PLc, Mi,
                                    NQc, Mi, PLc,
                                    (long)Mi * NQc, (long)128 * Mi, (long)NQc * PLc,
                                    1, Mi, mst, siv, NQc);
            }
        }

        // ---- Z = z_w[256,64] @ O_view[b][64,2304] (flat reinterpret) ----
        {
            dim3 grid(NQc / 128, CPc / 128, NB);
            gemm_k<128, 128, 8, 8, true, false, false, false>
                <<<grid, 256>>>(z_w, O, Z, CPc, NQc, PLc,
                                PLc, NQc, NQc,
                                0L, (long)NQc * PLc, (long)CPc * NQc,
                                1, PLc, nullptr, nullptr, 0);
        }

        // ---- BN ----
        bn_stats_k<<<CPc, 256>>>(Z, mean, istd);
        {
            long total4 = (long)NB * CPc * NQc / 4;
            bn_apply_k<<<(unsigned)(total4 / 256), 256>>>(
                Z, mean, istd, gamma, beta, out, i == 0 ? 1 : 0);
        }
    }
}

// round 3
// speedup vs baseline: 1.7801x; 1.0720x over previous
#include <cuda_runtime.h>
#include <math.h>

#define NB   4
#define CPc  256
#define PLc  64
#define NQc  2304

static const int CRs[5] = {64, 256, 512, 1024, 2048};
static const int Ms [5] = {2304, 2304, 576, 144, 36};

// ---------------------------------------------------------------------------
// Scratch
// ---------------------------------------------------------------------------
__device__ float    g_T  [NB * PLc * NQc];
__device__ float    g_PGw[2 * PLc * 2048];
__device__ float    g_PG [NB * 2 * PLc * NQc];
__device__ float    g_Lt [NB * NQc * NQc];
__device__ float    g_O  [NB * NQc * PLc];
__device__ float    g_Z  [NB * CPc * NQc];
__device__ unsigned g_mstU[NB * NQc];     // encoded column max
__device__ float    g_sum [NB * NQc];     // exp-sum per query
__device__ float    g_sinv[NB * NQc];     // 1/sum
__device__ float    g_stat[2 * CPc];      // BN sum, sumsq
__device__ float    g_mean[CPc];
__device__ float    g_istd[CPc];

// ---------------------------------------------------------------------------
// Helpers
// ---------------------------------------------------------------------------
__device__ __forceinline__ float fexp(float x)
{
    const float L2E = 1.4426950408889634f;
    float t = fmaf(x, L2E, 12582912.0f);
    float n = t - 12582912.0f;
    float f = fmaf(x, L2E, -n);
    float p = 1.33335581e-3f;
    p = fmaf(p, f, 9.61812911e-3f);
    p = fmaf(p, f, 5.55041087e-2f);
    p = fmaf(p, f, 2.40226507e-1f);
    p = fmaf(p, f, 6.93147180e-1f);
    p = fmaf(p, f, 1.0f);
    int ni = (int)n;
    ni = max(-126, min(127, ni));
    return p * __int_as_float((ni + 127) << 23);
}

// monotone float<->unsigned encoding for atomicMax; memset(0) == identity
__device__ __forceinline__ unsigned fenc(float x)
{
    unsigned b = __float_as_uint(x);
    return (b & 0x80000000u) ? ~b : (b | 0x80000000u);
}
__device__ __forceinline__ float fdec(unsigned k)
{
    return __uint_as_float((k & 0x80000000u) ? (k & 0x7FFFFFFFu) : ~k);
}

// ---------------------------------------------------------------------------
// Tiled SGEMM with global->register prefetch pipeline and fused extras.
//  TAR : A row-major [M,K] (else K-major [K,M])
//  TBR : B row-major [N,K] (else K-major [K,N])
//  EXPA: A elements -> exp(v - max[col]); accumulate per-column exp-sum
//  CMAX: epilogue column-max of C -> atomicMax(encoded)
//  DIVB: B elements scaled by sinv[flat>>6] (Z-GEMM normalization)
//  STAT: epilogue per-row (channel) sum/sumsq -> atomicAdd
//  ATOM: atomicAdd C (split-K)
// ---------------------------------------------------------------------------
template<int BM, int BN, int TM, int TN, bool TAR, bool TBR,
         bool EXPA, bool CMAX, bool DIVB, bool STAT, bool ATOM>
__global__ void __launch_bounds__(256) gemm_k(
    const float* __restrict__ A, const float* __restrict__ B, float* __restrict__ C,
    int M, int N, int K, int lda, int ldb, int ldc,
    long sA, long sB, long sC, int ksplit, int kchunk,
    const unsigned* __restrict__ mstIn, unsigned* __restrict__ mstOut,
    float* __restrict__ sumOut, const float* __restrict__ sinv,
    float* __restrict__ statOut, int sStat)
{
    constexpr int BK = 16;
    constexpr int LA = BM * BK / 1024;
    constexpr int LB = BN * BK / 1024;
    constexpr int MV = BM / 4, NV = BN / 4;
    constexpr int TX = BN / TN;
    static_assert((BM / TM) * (BN / TN) == 256, "256 threads");

    __shared__ float As[BK][BM];
    __shared__ float Bs[BK][BN + (TBR ? 1 : 0)];

    const int b  = blockIdx.z / ksplit;
    const int kz = blockIdx.z - b * ksplit;
    A += (long)b * sA;  B += (long)b * sB;  C += (long)b * sC;

    const int kbeg = kz * kchunk;
    const int kend = min(K, kbeg + kchunk);
    const int m0 = blockIdx.y * BM, n0 = blockIdx.x * BN;
    const int tid = threadIdx.x;
    const int ty = tid / TX, tx = tid - ty * TX;

    float4 ra[LA], rb[LB];
    float mxv[LA][4];
    float sacc[LA][4];

    if (EXPA) {
#pragma unroll
        for (int r = 0; r < LA; r++) {
            int e = tid + r * 256;
            int mq = e - (e / MV) * MV;
            int gm = m0 + mq * 4;
#pragma unroll
            for (int q = 0; q < 4; q++) {
                mxv[r][q] = fdec(mstIn[(long)b * sStat + gm + q]);
                sacc[r][q] = 0.f;
            }
        }
    }

    auto fetchA = [&](int k0) {
#pragma unroll
        for (int r = 0; r < LA; r++) {
            int e = tid + r * 256;
            float4 v = {0.f, 0.f, 0.f, 0.f};
            if (!TAR) {
                int k = e / MV, mq = e - k * MV;
                int gm = m0 + mq * 4;
                if (k0 + k < kend && gm + 3 < M) {
                    v = *(const float4*)(A + (long)(k0 + k) * lda + gm);
                    if (EXPA) {
                        v.x = fexp(v.x - mxv[r][0]); sacc[r][0] += v.x;
                        v.y = fexp(v.y - mxv[r][1]); sacc[r][1] += v.y;
                        v.z = fexp(v.z - mxv[r][2]); sacc[r][2] += v.z;
                        v.w = fexp(v.w - mxv[r][3]); sacc[r][3] += v.w;
                    }
                }
            } else {
                int m = e / 4, kq = e - m * 4;
                int gm = m0 + m, gk = k0 + kq * 4;
                if (gm < M) {
                    if (gk + 3 < kend) {
                        v = *(const float4*)(A + (long)gm * lda + gk);
                    } else {
                        float* vv = (float*)&v;
#pragma unroll
                        for (int q = 0; q < 4; q++)
                            if (gk + q < kend) vv[q] = A[(long)gm * lda + gk + q];
                    }
                }
            }
            ra[r] = v;
        }
    };
    auto storeA = [&]() {
#pragma unroll
        for (int r = 0; r < LA; r++) {
            int e = tid + r * 256;
            if (!TAR) {
                int k = e / MV, mq = e - k * MV;
                *(float4*)&As[k][mq * 4] = ra[r];
            } else {
                int m = e / 4, kq = e - m * 4;
                As[kq * 4 + 0][m] = ra[r].x; As[kq * 4 + 1][m] = ra[r].y;
                As[kq * 4 + 2][m] = ra[r].z; As[kq * 4 + 3][m] = ra[r].w;
            }
        }
    };
    auto fetchB = [&](int k0) {
#pragma unroll
        for (int r = 0; r < LB; r++) {
            int e = tid + r * 256;
            float4 v = {0.f, 0.f, 0.f, 0.f};
            if (!TBR) {
                int k = e / NV, nq = e - k * NV;
                int gn = n0 + nq * 4;
                if (k0 + k < kend && gn + 3 < N) {
                    long flat = (long)(k0 + k) * ldb + gn;
                    v = *(const float4*)(B + flat);
                    if (DIVB) {
                        float iv = sinv[(long)b * sStat + (int)(flat >> 6)];
                        v.x *= iv; v.y *= iv; v.z *= iv; v.w *= iv;
                    }
                }
            } else {
                int n = e / 4, kq = e - n * 4;
                int gn = n0 + n, gk = k0 + kq * 4;
                if (gn < N) {
                    if (gk + 3 < kend) {
                        v = *(const float4*)(B + (long)gn * ldb + gk);
                    } else {
                        float* vv = (float*)&v;
#pragma unroll
                        for (int q = 0; q < 4; q++)
                            if (gk + q < kend) vv[q] = B[(long)gn * ldb + gk + q];
                    }
                }
            }
            rb[r] = v;
        }
    };
    auto storeB = [&]() {
#pragma unroll
        for (int r = 0; r < LB; r++) {
            int e = tid + r * 256;
            if (!TBR) {
                int k = e / NV, nq = e - k * NV;
                *(float4*)&Bs[k][nq * 4] = rb[r];
            } else {
                int n = e / 4, kq = e - n * 4;
                Bs[kq * 4 + 0][n] = rb[r].x; Bs[kq * 4 + 1][n] = rb[r].y;
                Bs[kq * 4 + 2][n] = rb[r].z; Bs[kq * 4 + 3][n] = rb[r].w;
            }
        }
    };

    float acc[TM][TN];
#pragma unroll
    for (int i = 0; i < TM; i++)
#pragma unroll
        for (int j = 0; j < TN; j++) acc[i][j] = 0.f;

    fetchA(kbeg); fetchB(kbeg);
    storeA(); storeB();
    __syncthreads();

    for (int k0 = kbeg; k0 < kend; k0 += BK) {
        bool more = (k0 + BK) < kend;
        if (more) { fetchA(k0 + BK); fetchB(k0 + BK); }
#pragma unroll
        for (int kk = 0; kk < BK; kk++) {
            float a[TM], bb[TN];
#pragma unroll
            for (int i = 0; i < TM; i += 4)
                *(float4*)&a[i] = *(const float4*)&As[kk][ty * TM + i];
            if (!TBR) {
#pragma unroll
                for (int j = 0; j < TN; j += 4)
                    *(float4*)&bb[j] = *(const float4*)&Bs[kk][tx * TN + j];
            } else {
#pragma unroll
                for (int j = 0; j < TN; j++) bb[j] = Bs[kk][tx * TN + j];
            }
#pragma unroll
            for (int i = 0; i < TM; i++)
#pragma unroll
                for (int j = 0; j < TN; j++)
                    acc[i][j] = fmaf(a[i], bb[j], acc[i][j]);
        }
        __syncthreads();
        if (more) { storeA(); storeB(); __syncthreads(); }
    }

    // ---- C write ----
#pragma unroll
    for (int i = 0; i < TM; i++) {
        int gm = m0 + ty * TM + i;
        if (gm >= M) continue;
#pragma unroll
        for (int j = 0; j < TN; j++) {
            int gn = n0 + tx * TN + j;
            if (gn < N) {
                if (ATOM) atomicAdd(&C[(long)gm * ldc + gn], acc[i][j]);
                else      C[(long)gm * ldc + gn] = acc[i][j];
            }
        }
    }

    // ---- fused column max (logits) ----
    if (CMAX) {
        float* red = &As[0][0];          // TX*BN <= BK*BM floats
        float cm[TN];
#pragma unroll
        for (int j = 0; j < TN; j++) {
            cm[j] = acc[0][j];
#pragma unroll
            for (int i = 1; i < TM; i++) cm[j] = fmaxf(cm[j], acc[i][j]);
        }
#pragma unroll
        for (int j = 0; j < TN; j++) red[ty * BN + tx * TN + j] = cm[j];
        __syncthreads();
        if (tid < BN) {
            float m = red[tid];
#pragma unroll
            for (int t = 1; t < TX; t++) m = fmaxf(m, red[t * BN + tid]);
            atomicMax(&mstOut[(long)b * sStat + n0 + tid], fenc(m));
        }
    }

    // ---- fused exp-sum (O-GEMM) ----
    if (EXPA) {
        float* red = &As[0][0];
        if (tid < BM) red[tid] = 0.f;
        __syncthreads();
#pragma unroll
        for (int r = 0; r < LA; r++) {
            int e = tid + r * 256;
            int mq = e - (e / MV) * MV;
#pragma unroll
            for (int q = 0; q < 4; q++)
                atomicAdd(&red[mq * 4 + q], sacc[r][q]);
        }
        __syncthreads();
        if (tid < BM)
            atomicAdd(&sumOut[(long)b * sStat + m0 + tid], red[tid]);
    }

    // ---- fused BN partial stats (Z-GEMM) ----
    if (STAT) {
        float* red = &As[0][0];          // [0..BM) sum, [BM..2BM) sumsq
        if (tid < 2 * BM) red[tid] = 0.f;
        __syncthreads();
#pragma unroll
        for (int i = 0; i < TM; i++) {
            float s = 0.f, s2 = 0.f;
#pragma unroll
            for (int j = 0; j < TN; j++) {
                s += acc[i][j];
                s2 = fmaf(acc[i][j], acc[i][j], s2);
            }
            atomicAdd(&red[ty * TM + i], s);
            atomicAdd(&red[BM + ty * TM + i], s2);
        }
        __syncthreads();
        if (tid < BM && m0 + tid < M) {
            atomicAdd(&statOut[m0 + tid], red[tid]);
            atomicAdd(&statOut[CPc + m0 + tid], red[BM + tid]);
        }
    }
}

// ---------------------------------------------------------------------------
// Small kernels
// ---------------------------------------------------------------------------
__global__ void sinv_k(const float* __restrict__ s, float* __restrict__ si)
{
    int i = blockIdx.x * 256 + threadIdx.x;
    si[i] = 1.0f / s[i];
}

__global__ void bn_finalize_k(const float* __restrict__ stat,
                              float* __restrict__ mean, float* __restrict__ istd)
{
    int c = threadIdx.x;
    const float inv = 1.0f / (float)(NB * NQc);
    float m = stat[c] * inv;
    float v = stat[CPc + c] * inv - m * m;
    mean[c] = m;
    istd[c] = rsqrtf(v + 1e-5f);
}

__global__ void bn_apply_k(const float* __restrict__ Z,
                           const float* __restrict__ mean, const float* __restrict__ istd,
                           const float* __restrict__ gamma, const float* __restrict__ beta,
                           float* __restrict__ out, int first)
{
    long i = ((long)blockIdx.x * 256 + threadIdx.x) * 4;
    int c = (int)((i / NQc) % CPc);
    float a = istd[c] * gamma[c];
    float bb = fmaf(-mean[c], a, beta[c]);
    float4 z = *(const float4*)(Z + i);
    float4 v;
    v.x = fmaf(z.x, a, bb); v.y = fmaf(z.y, a, bb);
    v.z = fmaf(z.z, a, bb); v.w = fmaf(z.w, a, bb);
    if (first) {
        *(float4*)(out + i) = v;
    } else {
        float4 o = *(const float4*)(out + i);
        o.x += v.x; o.y += v.y; o.z += v.z; o.w += v.w;
        *(float4*)(out + i) = o;
    }
}

// ---------------------------------------------------------------------------
// Host launch
// ---------------------------------------------------------------------------
extern "C" void kernel_launch(void* const* d_in, const int* in_sizes, int n_in,
                              void* d_out, int out_size)
{
    (void)in_sizes; (void)n_in; (void)out_size;

    const float* persp = (const float*)d_in[0];
    const float* resp[5] = {
        (const float*)d_in[1], (const float*)d_in[2], (const float*)d_in[3],
        (const float*)d_in[4], (const float*)d_in[5] };
    const float* t_w = (const float*)d_in[6];
    const float* z_w = (const float*)d_in[7];
    float* out = (float*)d_out;

    float *T, *PGw, *PG, *Lt, *O, *Z, *sum, *sinv, *stat, *mean, *istd;
    unsigned* mstU;
    cudaGetSymbolAddress((void**)&T,    g_T);
    cudaGetSymbolAddress((void**)&PGw,  g_PGw);
    cudaGetSymbolAddress((void**)&PG,   g_PG);
    cudaGetSymbolAddress((void**)&Lt,   g_Lt);
    cudaGetSymbolAddress((void**)&O,    g_O);
    cudaGetSymbolAddress((void**)&Z,    g_Z);
    cudaGetSymbolAddress((void**)&mstU, g_mstU);
    cudaGetSymbolAddress((void**)&sum,  g_sum);
    cudaGetSymbolAddress((void**)&sinv, g_sinv);
    cudaGetSymbolAddress((void**)&stat, g_stat);
    cudaGetSymbolAddress((void**)&mean, g_mean);
    cudaGetSymbolAddress((void**)&istd, g_istd);

    // ---- T = t_w[64,256] @ persp[b][256,2304] ----
    gemm_k<64, 128, 4, 8, true, false, false, false, false, false, false>
        <<<dim3(NQc / 128, 1, NB), 256>>>(
            t_w, persp, T, PLc, NQc, CPc, CPc, NQc, NQc,
            0L, (long)CPc * NQc, (long)PLc * NQc, 1, CPc,
            nullptr, nullptr, nullptr, nullptr, nullptr, 0);

    static const int OKS[5] = {4, 4, 2, 1, 1};

    for (int i = 0; i < 5; i++) {
        const int Cr = CRs[i];
        const int Mi = Ms[i];
        const float* p_w   = (const float*)d_in[8  + 4 * i];
        const float* g_wt  = (const float*)d_in[9  + 4 * i];
        const float* gamma = (const float*)d_in[10 + 4 * i];
        const float* beta  = (const float*)d_in[11 + 4 * i];

        cudaMemcpyAsync(PGw,            p_w, (size_t)PLc * Cr * 4,
                        cudaMemcpyDeviceToDevice, 0);
        cudaMemcpyAsync(PGw + PLc * Cr, g_wt, (size_t)PLc * Cr * 4,
                        cudaMemcpyDeviceToDevice, 0);

        // ---- PG = PGw[128,Cr] @ resp[b][Cr,Mi]  (split-K over Cr) ----
        {
            int ks = Cr / 64;
            dim3 grid((Mi + 127) / 128, 1, NB * ks);
            if (ks > 1) {
                cudaMemsetAsync(PG, 0, (size_t)NB * 128 * Mi * 4, 0);
                gemm_k<128, 128, 8, 8, true, false, false, false, false, false, true>
                    <<<grid, 256>>>(PGw, resp[i], PG, 128, Mi, Cr, Cr, Mi, Mi,
                                    0L, (long)Cr * Mi, (long)128 * Mi, ks, 64,
                                    nullptr, nullptr, nullptr, nullptr, nullptr, 0);
            } else {
                gemm_k<128, 128, 8, 8, true, false, false, false, false, false, false>
                    <<<grid, 256>>>(PGw, resp[i], PG, 128, Mi, Cr, Cr, Mi, Mi,
                                    0L, (long)Cr * Mi, (long)128 * Mi, 1, Cr,
                                    nullptr, nullptr, nullptr, nullptr, nullptr, 0);
            }
        }

        // ---- Lt[b][Mi][2304] = P^T @ T, with fused per-column max ----
        cudaMemsetAsync(mstU, 0, (size_t)NB * NQc * 4, 0);
        {
            dim3 grid(NQc / 128, (Mi + 127) / 128, NB);
            gemm_k<128, 128, 8, 8, false, false, false, true, false, false, false>
                <<<grid, 256>>>(PG, T, Lt, Mi, NQc, PLc, Mi, NQc, NQc,
                                (long)128 * Mi, (long)PLc * NQc, (long)Mi * NQc,
                                1, PLc,
                                nullptr, mstU, nullptr, nullptr, nullptr, NQc);
        }

        // ---- O = exp(Lt - max)^T @ G^T  (unnormalized; fused exp-sum) ----
        cudaMemsetAsync(sum, 0, (size_t)NB * NQc * 4, 0);
        {
            int ks = OKS[i];
            int kchunk = (Mi + ks - 1) / ks;
            dim3 grid(1, NQc / 128, NB * ks);
            if (ks > 1) {
                cudaMemsetAsync(O, 0, (size_t)NB * NQc * PLc * 4, 0);
                gemm_k<128, 64, 8, 4, false, true, true, false, false, false, true>
                    <<<grid, 256>>>(Lt, PG + (long)PLc * Mi, O, NQc, PLc, Mi,
                                    NQc, Mi, PLc,
                                    (long)Mi * NQc, (long)128 * Mi, (long)NQc * PLc,
                                    ks, kchunk,
                                    mstU, nullptr, sum, nullptr, nullptr, NQc);
            } else {
                gemm_k<128, 64, 8, 4, false, true, true, false, false, false, false>
                    <<<grid, 256>>>(Lt, PG + (long)PLc * Mi, O, NQc, PLc, Mi,
                                    NQc, Mi, PLc,
                                    (long)Mi * NQc, (long)128 * Mi, (long)NQc * PLc,
                                    1, Mi,
                                    mstU, nullptr, sum, nullptr, nullptr, NQc);
            }
        }
        sinv_k<<<NB * NQc / 256, 256>>>(sum, sinv);

        // ---- Z = z_w @ (O/sum)_view, with fused BN partial stats ----
        cudaMemsetAsync(stat, 0, (size_t)2 * CPc * 4, 0);
        {
            dim3 grid(NQc / 128, CPc / 128, NB);
            gemm_k<128, 128, 8, 8, true, false, false, false, true, true, false>
                <<<grid, 256>>>(z_w, O, Z, CPc, NQc, PLc, PLc, NQc, NQc,
                                0L, (long)NQc * PLc, (long)CPc * NQc, 1, PLc,
                                nullptr, nullptr, nullptr, sinv, stat, NQc);
        }

        bn_finalize_k<<<1, 256>>>(stat, mean, istd);
        {
            long total4 = (long)NB * CPc * NQc / 4;
            bn_apply_k<<<(unsigned)(total4 / 256), 256>>>(
                Z, mean, istd, gamma, beta, out, i == 0 ? 1 : 0);
        }
    }
}

// round 4
// speedup vs baseline: 1.8964x; 1.0653x over previous
#include <cuda_runtime.h>
#include <math.h>

#define NB   4
#define CPc  256
#define PLc  64
#define NQc  2304

static const int CRs[5] = {64, 256, 512, 1024, 2048};
static const int Ms [5] = {2304, 2304, 576, 144, 36};

// ---------------------------------------------------------------------------
// Scratch
// ---------------------------------------------------------------------------
__device__ float    g_T  [NB * PLc * NQc];
__device__ float    g_PGw[2 * PLc * 2048];
__device__ float    g_PG [NB * 2 * PLc * NQc];
__device__ float    g_Lt [NB * NQc * NQc];
__device__ float    g_O  [NB * NQc * PLc];
__device__ float    g_Z  [NB * CPc * NQc];
__device__ unsigned g_mstU[NB * NQc];
__device__ float    g_sum [NB * NQc];
__device__ float    g_sinv[NB * NQc];
__device__ float    g_stat[2 * CPc];
__device__ float    g_mean[CPc];
__device__ float    g_istd[CPc];

// ---------------------------------------------------------------------------
// Helpers
// ---------------------------------------------------------------------------
__device__ __forceinline__ float fexp(float x)
{
    const float L2E = 1.4426950408889634f;
    float t = fmaf(x, L2E, 12582912.0f);
    float n = t - 12582912.0f;
    float f = fmaf(x, L2E, -n);
    float p = 1.33335581e-3f;
    p = fmaf(p, f, 9.61812911e-3f);
    p = fmaf(p, f, 5.55041087e-2f);
    p = fmaf(p, f, 2.40226507e-1f);
    p = fmaf(p, f, 6.93147180e-1f);
    p = fmaf(p, f, 1.0f);
    int ni = (int)n;
    ni = max(-126, min(127, ni));
    return p * __int_as_float((ni + 127) << 23);
}

__device__ __forceinline__ unsigned fenc(float x)
{
    unsigned b = __float_as_uint(x);
    return (b & 0x80000000u) ? ~b : (b | 0x80000000u);
}
__device__ __forceinline__ float fdec(unsigned k)
{
    return __uint_as_float((k & 0x80000000u) ? (k & 0x7FFFFFFFu) : ~k);
}

// ---------------------------------------------------------------------------
// Tiled SGEMM, double-buffered smem (ONE sync per k-tile), reg prefetch,
// fused softmax / BN extras. Flags as before.
// ---------------------------------------------------------------------------
template<int BM, int BN, int TM, int TN, bool TAR, bool TBR,
         bool EXPA, bool CMAX, bool DIVB, bool STAT, bool ATOM>
__global__ void __launch_bounds__(256) gemm_k(
    const float* __restrict__ A, const float* __restrict__ B, float* __restrict__ C,
    int M, int N, int K, int lda, int ldb, int ldc,
    long sA, long sB, long sC, int ksplit, int kchunk,
    const unsigned* __restrict__ mstIn, unsigned* __restrict__ mstOut,
    float* __restrict__ sumOut, const float* __restrict__ sinv,
    float* __restrict__ statOut, int sStat)
{
    constexpr int BK = 16;
    constexpr int LA = BM * BK / 1024;
    constexpr int LB = BN * BK / 1024;
    constexpr int MV = BM / 4, NV = BN / 4;
    constexpr int TX = BN / TN;
    static_assert((BM / TM) * (BN / TN) == 256, "256 threads");

    __shared__ float As[2][BK][BM];
    __shared__ float Bs[2][BK][BN + (TBR ? 1 : 0)];

    const int b  = blockIdx.z / ksplit;
    const int kz = blockIdx.z - b * ksplit;
    A += (long)b * sA;  B += (long)b * sB;  C += (long)b * sC;

    const int kbeg = kz * kchunk;
    const int kend = min(K, kbeg + kchunk);
    const int m0 = blockIdx.y * BM, n0 = blockIdx.x * BN;
    const int tid = threadIdx.x;
    const int ty = tid / TX, tx = tid - ty * TX;

    float4 ra[LA], rb[LB];
    float mxv[LA][4];
    float sacc[LA][4];

    if (EXPA) {
#pragma unroll
        for (int r = 0; r < LA; r++) {
            int e = tid + r * 256;
            int mq = e - (e / MV) * MV;
            int gm = m0 + mq * 4;
#pragma unroll
            for (int q = 0; q < 4; q++) {
                mxv[r][q] = fdec(mstIn[(long)b * sStat + gm + q]);
                sacc[r][q] = 0.f;
            }
        }
    }

    auto fetchA = [&](int k0) {
#pragma unroll
        for (int r = 0; r < LA; r++) {
            int e = tid + r * 256;
            float4 v = {0.f, 0.f, 0.f, 0.f};
            if (!TAR) {
                int k = e / MV, mq = e - k * MV;
                int gm = m0 + mq * 4;
                if (k0 + k < kend && gm + 3 < M) {
                    v = *(const float4*)(A + (long)(k0 + k) * lda + gm);
                    if (EXPA) {
                        v.x = fexp(v.x - mxv[r][0]); sacc[r][0] += v.x;
                        v.y = fexp(v.y - mxv[r][1]); sacc[r][1] += v.y;
                        v.z = fexp(v.z - mxv[r][2]); sacc[r][2] += v.z;
                        v.w = fexp(v.w - mxv[r][3]); sacc[r][3] += v.w;
                    }
                }
            } else {
                int m = e / 4, kq = e - m * 4;
                int gm = m0 + m, gk = k0 + kq * 4;
                if (gm < M) {
                    if (gk + 3 < kend) {
                        v = *(const float4*)(A + (long)gm * lda + gk);
                    } else {
                        float* vv = (float*)&v;
#pragma unroll
                        for (int q = 0; q < 4; q++)
                            if (gk + q < kend) vv[q] = A[(long)gm * lda + gk + q];
                    }
                }
            }
            ra[r] = v;
        }
    };
    auto storeA = [&](int buf) {
#pragma unroll
        for (int r = 0; r < LA; r++) {
            int e = tid + r * 256;
            if (!TAR) {
                int k = e / MV, mq = e - k * MV;
                *(float4*)&As[buf][k][mq * 4] = ra[r];
            } else {
                int m = e / 4, kq = e - m * 4;
                As[buf][kq * 4 + 0][m] = ra[r].x; As[buf][kq * 4 + 1][m] = ra[r].y;
                As[buf][kq * 4 + 2][m] = ra[r].z; As[buf][kq * 4 + 3][m] = ra[r].w;
            }
        }
    };
    auto fetchB = [&](int k0) {
#pragma unroll
        for (int r = 0; r < LB; r++) {
            int e = tid + r * 256;
            float4 v = {0.f, 0.f, 0.f, 0.f};
            if (!TBR) {
                int k = e / NV, nq = e - k * NV;
                int gn = n0 + nq * 4;
                if (k0 + k < kend && gn + 3 < N) {
                    long flat = (long)(k0 + k) * ldb + gn;
                    v = *(const float4*)(B + flat);
                    if (DIVB) {
                        float iv = sinv[(long)b * sStat + (int)(flat >> 6)];
                        v.x *= iv; v.y *= iv; v.z *= iv; v.w *= iv;
                    }
                }
            } else {
                int n = e / 4, kq = e - n * 4;
                int gn = n0 + n, gk = k0 + kq * 4;
                if (gn < N) {
                    if (gk + 3 < kend) {
                        v = *(const float4*)(B + (long)gn * ldb + gk);
                    } else {
                        float* vv = (float*)&v;
#pragma unroll
                        for (int q = 0; q < 4; q++)
                            if (gk + q < kend) vv[q] = B[(long)gn * ldb + gk + q];
                    }
                }
            }
            rb[r] = v;
        }
    };
    auto storeB = [&](int buf) {
#pragma unroll
        for (int r = 0; r < LB; r++) {
            int e = tid + r * 256;
            if (!TBR) {
                int k = e / NV, nq = e - k * NV;
                *(float4*)&Bs[buf][k][nq * 4] = rb[r];
            } else {
                int n = e / 4, kq = e - n * 4;
                Bs[buf][kq * 4 + 0][n] = rb[r].x; Bs[buf][kq * 4 + 1][n] = rb[r].y;
                Bs[buf][kq * 4 + 2][n] = rb[r].z; Bs[buf][kq * 4 + 3][n] = rb[r].w;
            }
        }
    };

    float acc[TM][TN];
#pragma unroll
    for (int i = 0; i < TM; i++)
#pragma unroll
        for (int j = 0; j < TN; j++) acc[i][j] = 0.f;

    const int nkt = (kend - kbeg + BK - 1) / BK;

    fetchA(kbeg); fetchB(kbeg);
    storeA(0); storeB(0);
    __syncthreads();

    for (int t = 0; t < nkt; t++) {
        const int cur = t & 1, nxt = cur ^ 1;
        const bool more = (t + 1) < nkt;
        if (more) { fetchA(kbeg + (t + 1) * BK); fetchB(kbeg + (t + 1) * BK); }

#pragma unroll
        for (int kk = 0; kk < BK; kk++) {
            float a[TM], bb[TN];
#pragma unroll
            for (int i = 0; i < TM; i += 4)
                *(float4*)&a[i] = *(const float4*)&As[cur][kk][ty * TM + i];
            if (!TBR) {
#pragma unroll
                for (int j = 0; j < TN; j += 4)
                    *(float4*)&bb[j] = *(const float4*)&Bs[cur][kk][tx * TN + j];
            } else {
#pragma unroll
                for (int j = 0; j < TN; j++) bb[j] = Bs[cur][kk][tx * TN + j];
            }
#pragma unroll
            for (int i = 0; i < TM; i++)
#pragma unroll
                for (int j = 0; j < TN; j++)
                    acc[i][j] = fmaf(a[i], bb[j], acc[i][j]);
        }

        if (more) { storeA(nxt); storeB(nxt); }
        __syncthreads();
    }

    // ---- C write ----
#pragma unroll
    for (int i = 0; i < TM; i++) {
        int gm = m0 + ty * TM + i;
        if (gm >= M) continue;
#pragma unroll
        for (int j = 0; j < TN; j++) {
            int gn = n0 + tx * TN + j;
            if (gn < N) {
                if (ATOM) atomicAdd(&C[(long)gm * ldc + gn], acc[i][j]);
                else      C[(long)gm * ldc + gn] = acc[i][j];
            }
        }
    }

    // ---- fused column max (logits) ----
    if (CMAX) {
        float* red = &As[0][0][0];
        float cm[TN];
#pragma unroll
        for (int j = 0; j < TN; j++) {
            cm[j] = acc[0][j];
#pragma unroll
            for (int i = 1; i < TM; i++) cm[j] = fmaxf(cm[j], acc[i][j]);
        }
#pragma unroll
        for (int j = 0; j < TN; j++) red[ty * BN + tx * TN + j] = cm[j];
        __syncthreads();
        if (tid < BN) {
            float m = red[tid];
#pragma unroll
            for (int t = 1; t < TX; t++) m = fmaxf(m, red[t * BN + tid]);
            atomicMax(&mstOut[(long)b * sStat + n0 + tid], fenc(m));
        }
    }

    // ---- fused exp-sum (O-GEMM) ----
    if (EXPA) {
        float* red = &As[0][0][0];
        if (tid < BM) red[tid] = 0.f;
        __syncthreads();
#pragma unroll
        for (int r = 0; r < LA; r++) {
            int e = tid + r * 256;
            int mq = e - (e / MV) * MV;
#pragma unroll
            for (int q = 0; q < 4; q++)
                atomicAdd(&red[mq * 4 + q], sacc[r][q]);
        }
        __syncthreads();
        if (tid < BM)
            atomicAdd(&sumOut[(long)b * sStat + m0 + tid], red[tid]);
    }

    // ---- fused BN partial stats (Z-GEMM) ----
    if (STAT) {
        float* red = &As[0][0][0];
        if (tid < 2 * BM) red[tid] = 0.f;
        __syncthreads();
#pragma unroll
        for (int i = 0; i < TM; i++) {
            float s = 0.f, s2 = 0.f;
#pragma unroll
            for (int j = 0; j < TN; j++) {
                s += acc[i][j];
                s2 = fmaf(acc[i][j], acc[i][j], s2);
            }
            atomicAdd(&red[ty * TM + i], s);
            atomicAdd(&red[BM + ty * TM + i], s2);
        }
        __syncthreads();
        if (tid < BM && m0 + tid < M) {
            atomicAdd(&statOut[m0 + tid], red[tid]);
            atomicAdd(&statOut[CPc + m0 + tid], red[BM + tid]);
        }
    }
}

// ---------------------------------------------------------------------------
// Small kernels
// ---------------------------------------------------------------------------
__global__ void sinv_k(const float* __restrict__ s, float* __restrict__ si)
{
    int i = blockIdx.x * 256 + threadIdx.x;
    si[i] = 1.0f / s[i];
}

__global__ void bn_finalize_k(const float* __restrict__ stat,
                              float* __restrict__ mean, float* __restrict__ istd)
{
    int c = threadIdx.x;
    const float inv = 1.0f / (float)(NB * NQc);
    float m = stat[c] * inv;
    float v = stat[CPc + c] * inv - m * m;
    mean[c] = m;
    istd[c] = rsqrtf(v + 1e-5f);
}

__global__ void bn_apply_k(const float* __restrict__ Z,
                           const float* __restrict__ mean, const float* __restrict__ istd,
                           const float* __restrict__ gamma, const float* __restrict__ beta,
                           float* __restrict__ out, int first)
{
    long i = ((long)blockIdx.x * 256 + threadIdx.x) * 4;
    int c = (int)((i / NQc) % CPc);
    float a = istd[c] * gamma[c];
    float bb = fmaf(-mean[c], a, beta[c]);
    float4 z = *(const float4*)(Z + i);
    float4 v;
    v.x = fmaf(z.x, a, bb); v.y = fmaf(z.y, a, bb);
    v.z = fmaf(z.z, a, bb); v.w = fmaf(z.w, a, bb);
    if (first) {
        *(float4*)(out + i) = v;
    } else {
        float4 o = *(const float4*)(out + i);
        o.x += v.x; o.y += v.y; o.z += v.z; o.w += v.w;
        *(float4*)(out + i) = o;
    }
}

// ---------------------------------------------------------------------------
// Host launch
// ---------------------------------------------------------------------------
extern "C" void kernel_launch(void* const* d_in, const int* in_sizes, int n_in,
                              void* d_out, int out_size)
{
    (void)in_sizes; (void)n_in; (void)out_size;

    const float* persp = (const float*)d_in[0];
    const float* resp[5] = {
        (const float*)d_in[1], (const float*)d_in[2], (const float*)d_in[3],
        (const float*)d_in[4], (const float*)d_in[5] };
    const float* t_w = (const float*)d_in[6];
    const float* z_w = (const float*)d_in[7];
    float* out = (float*)d_out;

    float *T, *PGw, *PG, *Lt, *O, *Z, *sum, *sinv, *stat, *mean, *istd;
    unsigned* mstU;
    cudaGetSymbolAddress((void**)&T,    g_T);
    cudaGetSymbolAddress((void**)&PGw,  g_PGw);
    cudaGetSymbolAddress((void**)&PG,   g_PG);
    cudaGetSymbolAddress((void**)&Lt,   g_Lt);
    cudaGetSymbolAddress((void**)&O,    g_O);
    cudaGetSymbolAddress((void**)&Z,    g_Z);
    cudaGetSymbolAddress((void**)&mstU, g_mstU);
    cudaGetSymbolAddress((void**)&sum,  g_sum);
    cudaGetSymbolAddress((void**)&sinv, g_sinv);
    cudaGetSymbolAddress((void**)&stat, g_stat);
    cudaGetSymbolAddress((void**)&mean, g_mean);
    cudaGetSymbolAddress((void**)&istd, g_istd);

    // ---- T = t_w[64,256] @ persp ----
    gemm_k<64, 128, 4, 8, true, false, false, false, false, false, false>
        <<<dim3(NQc / 128, 1, NB), 256>>>(
            t_w, persp, T, PLc, NQc, CPc, CPc, NQc, NQc,
            0L, (long)CPc * NQc, (long)PLc * NQc, 1, CPc,
            nullptr, nullptr, nullptr, nullptr, nullptr, 0);

    static const int OKS[5] = {8, 8, 4, 2, 1};

    for (int i = 0; i < 5; i++) {
        const int Cr = CRs[i];
        const int Mi = Ms[i];
        const float* p_w   = (const float*)d_in[8  + 4 * i];
        const float* g_wt  = (const float*)d_in[9  + 4 * i];
        const float* gamma = (const float*)d_in[10 + 4 * i];
        const float* beta  = (const float*)d_in[11 + 4 * i];

        cudaMemcpyAsync(PGw,            p_w, (size_t)PLc * Cr * 4,
                        cudaMemcpyDeviceToDevice, 0);
        cudaMemcpyAsync(PGw + PLc * Cr, g_wt, (size_t)PLc * Cr * 4,
                        cudaMemcpyDeviceToDevice, 0);

        // ---- PG = PGw[128,Cr] @ resp  (split-K chunk 128) ----
        {
            int ks = Cr >= 128 ? Cr / 128 : 1;
            int kchunk = Cr / ks;
            dim3 grid((Mi + 127) / 128, 1, NB * ks);
            if (ks > 1) {
                cudaMemsetAsync(PG, 0, (size_t)NB * 128 * Mi * 4, 0);
                gemm_k<128, 128, 8, 8, true, false, false, false, false, false, true>
                    <<<grid, 256>>>(PGw, resp[i], PG, 128, Mi, Cr, Cr, Mi, Mi,
                                    0L, (long)Cr * Mi, (long)128 * Mi, ks, kchunk,
                                    nullptr, nullptr, nullptr, nullptr, nullptr, 0);
            } else {
                gemm_k<128, 128, 8, 8, true, false, false, false, false, false, false>
                    <<<grid, 256>>>(PGw, resp[i], PG, 128, Mi, Cr, Cr, Mi, Mi,
                                    0L, (long)Cr * Mi, (long)128 * Mi, 1, Cr,
                                    nullptr, nullptr, nullptr, nullptr, nullptr, 0);
            }
        }

        // ---- Lt = P^T @ T with fused column max ----
        cudaMemsetAsync(mstU, 0, (size_t)NB * NQc * 4, 0);
        {
            dim3 grid(NQc / 128, (Mi + 127) / 128, NB);
            gemm_k<128, 128, 8, 8, false, false, false, true, false, false, false>
                <<<grid, 256>>>(PG, T, Lt, Mi, NQc, PLc, Mi, NQc, NQc,
                                (long)128 * Mi, (long)PLc * NQc, (long)Mi * NQc,
                                1, PLc,
                                nullptr, mstU, nullptr, nullptr, nullptr, NQc);
        }

        // ---- O = exp(Lt - max)^T @ G^T  (fused exp-sum; split-K) ----
        cudaMemsetAsync(sum, 0, (size_t)NB * NQc * 4, 0);
        {
            int ks = OKS[i];
            int kchunk = (Mi + ks - 1) / ks;
            dim3 grid(1, NQc / 128, NB * ks);
            if (ks > 1) {
                cudaMemsetAsync(O, 0, (size_t)NB * NQc * PLc * 4, 0);
                gemm_k<128, 64, 8, 4, false, true, true, false, false, false, true>
                    <<<grid, 256>>>(Lt, PG + (long)PLc * Mi, O, NQc, PLc, Mi,
                                    NQc, Mi, PLc,
                                    (long)Mi * NQc, (long)128 * Mi, (long)NQc * PLc,
                                    ks, kchunk,
                                    mstU, nullptr, sum, nullptr, nullptr, NQc);
            } else {
                gemm_k<128, 64, 8, 4, false, true, true, false, false, false, false>
                    <<<grid, 256>>>(Lt, PG + (long)PLc * Mi, O, NQc, PLc, Mi,
                                    NQc, Mi, PLc,
                                    (long)Mi * NQc, (long)128 * Mi, (long)NQc * PLc,
                                    1, Mi,
                                    mstU, nullptr, sum, nullptr, nullptr, NQc);
            }
        }
        sinv_k<<<NB * NQc / 256, 256>>>(sum, sinv);

        // ---- Z = z_w @ (O/sum)_view with fused BN stats ----
        cudaMemsetAsync(stat, 0, (size_t)2 * CPc * 4, 0);
        {
            dim3 grid(NQc / 128, CPc / 128, NB);
            gemm_k<128, 128, 8, 8, true, false, false, false, true, true, false>
                <<<grid, 256>>>(z_w, O, Z, CPc, NQc, PLc, PLc, NQc, NQc,
                                0L, (long)NQc * PLc, (long)CPc * NQc, 1, PLc,
                                nullptr, nullptr, nullptr, sinv, stat, NQc);
        }

        bn_finalize_k<<<1, 256>>>(stat, mean, istd);
        {
            long total4 = (long)NB * CPc * NQc / 4;
            bn_apply_k<<<(unsigned)(total4 / 256), 256>>>(
                Z, mean, istd, gamma, beta, out, i == 0 ? 1 : 0);
        }
    }
}